// round 17
// baseline (speedup 1.0000x reference)
#include <cuda_runtime.h>
#include <cuda_fp16.h>
#include <cstdint>

// ---------------- problem constants ----------------
#define NIMG 8
#define NC   32
#define NV   128
#define HH   128
#define WW   128
#define CIN  64
#define CC   65
#define CMID 256
#define HP   130
#define KREAL 585          // 65 * 9, k = ci*9 + ky*3 + kx
#define KPAD  640
#define CHUNK 64
#define NCH   10

// shifted-input buffer strides (fp16 elements); rows are 128 wide, 130 tall
#define CS  (HP * 128)           // per channel  = 16640
#define NS  (CC * CS)            // per image    = 1081600
#define KXS (NIMG * NS)          // per kx shift = 8652800

// ---------------- device scratch ----------------
__device__ float    g_Fx[NC * NV * WW];
__device__ float    g_Fy[NC * NV * HH];
__device__ uint16_t g_Xs[3 * KXS];       // 3 kx-shifted fp16 padded inputs (52MB)
__device__ uint4    g_wBh4[NCH * 2048];  // pre-swizzled fp16 weight planes
__device__ int      g_batch[NC];

// ---------------- helpers ----------------
__device__ __forceinline__ uint32_t smem_u32(const void* p) {
    uint32_t a;
    asm("{ .reg .u64 t; cvta.to.shared.u64 t, %1; cvt.u32.u64 %0, t; }"
        : "=r"(a) : "l"(p));
    return a;
}
__device__ __forceinline__ void ldm_x4_trans(uint32_t* r, uint32_t a) {
    asm volatile("ldmatrix.sync.aligned.m8n8.x4.trans.shared.b16 {%0,%1,%2,%3}, [%4];"
        : "=r"(r[0]), "=r"(r[1]), "=r"(r[2]), "=r"(r[3]) : "r"(a));
}
__device__ __forceinline__ void ldm_x4(uint32_t* r, uint32_t a) {
    asm volatile("ldmatrix.sync.aligned.m8n8.x4.shared.b16 {%0,%1,%2,%3}, [%4];"
        : "=r"(r[0]), "=r"(r[1]), "=r"(r[2]), "=r"(r[3]) : "r"(a));
}
__device__ __forceinline__ void mma_fp16(float* d, const uint32_t* a, const uint32_t* b) {
    asm volatile("mma.sync.aligned.m16n8k16.row.col.f32.f16.f16.f32 "
        "{%0,%1,%2,%3}, {%4,%5,%6,%7}, {%8,%9}, {%0,%1,%2,%3};"
        : "+f"(d[0]), "+f"(d[1]), "+f"(d[2]), "+f"(d[3])
        : "r"(a[0]), "r"(a[1]), "r"(a[2]), "r"(a[3]), "r"(b[0]), "r"(b[1]));
}
#define CP_ASYNC16(dst, src) \
    asm volatile("cp.async.cg.shared.global [%0], [%1], 16;" \
                 :: "r"(dst), "l"(src) : "memory")
#define CP_ASYNC16Z(dst, src, sz) \
    asm volatile("cp.async.cg.shared.global [%0], [%1], 16, %2;" \
                 :: "r"(dst), "l"(src), "r"(sz) : "memory")
#define CP_COMMIT()  asm volatile("cp.async.commit_group;" ::: "memory")
#define CP_WAIT0()   asm volatile("cp.async.wait_group 0;" ::: "memory")

// ---------------- prep kernel: tables + batch + fill + zero + wsplit + oinit
// ranges: [0, 2048)                 tables (2 v-rows per block)
//         [2048, 2049)              batch detect
//         [2049, 4097)              fill (grid-stride, R10-exact logic)
//         [4097, 6186)              frame zeroing
//         [6186, 6826)              weight split
//         [6826, 7850)              out init
#define TAB_BLOCKS   2048
#define BATCH_BLOCKS 1
#define FILL_BLOCKS  2048
#define ZERO_BLOCKS  2089
#define WS_BLOCKS    640
#define OINIT_BLOCKS 1024
#define R_TAB   TAB_BLOCKS
#define R_BATCH (R_TAB + BATCH_BLOCKS)
#define R_FILL  (R_BATCH + FILL_BLOCKS)
#define R_ZERO  (R_FILL + ZERO_BLOCKS)
#define R_WS    (R_ZERO + WS_BLOCKS)
#define R_OINIT (R_WS + OINIT_BLOCKS)
__global__ void k_prep(const float* __restrict__ contour, const int* bi,
                       const float* __restrict__ feat, const float* __restrict__ w1,
                       const float* __restrict__ b2, float* __restrict__ outp) {
    int bid = blockIdx.x;
    int tid = threadIdx.x;
    if (bid < R_TAB) {
        int g = bid * 2 + (tid >> 7);       // cv index 0..4095
        int v = g & 127, c = g >> 7, t = tid & 127;
        float cx = contour[(c * NV + v) * 2 + 0] * 0.25f;
        float cy = contour[(c * NV + v) * 2 + 1] * 0.25f;
        float dx = (float)t - cx, dy = (float)t - cy;
        const float INV2PI = 0.15915494309189535f;
        g_Fx[(c * NV + v) * WW + t] = INV2PI * __expf(-0.5f * dx * dx);
        g_Fy[(c * NV + v) * HH + t] = __expf(-0.5f * dy * dy);
    } else if (bid < R_BATCH) {
        __shared__ int s_is64;
        if (tid == 0) {
            int is64 = 1;
            #pragma unroll
            for (int i = 0; i < 16; i++)
                if (bi[2 * i + 1] != 0) is64 = 0;
            s_is64 = is64;
        }
        __syncthreads();
        if (tid < NC) g_batch[tid] = s_is64 ? bi[2 * tid] : bi[tid];
    } else if (bid < R_FILL) {
        const int total = NIMG * CIN * HH * WW;
        for (int idx = (bid - R_BATCH) * 256 + tid; idx < total;
             idx += FILL_BLOCKS * 256) {
            int x = idx & 127;
            int y = (idx >> 7) & 127;
            int ci = (idx >> 14) & 63;
            int n = idx >> 20;
            uint16_t v = __half_as_ushort(__float2half_rn(feat[idx]));
            int base = n * NS + (ci + 1) * CS + (y + 1) * 128;
            #pragma unroll
            for (int kx = 0; kx < 3; kx++) {
                int xq = x + 1 - kx;
                if (xq >= 0 && xq < 128) g_Xs[kx * KXS + base + xq] = v;
            }
        }
    } else if (bid < R_ZERO) {
        int idx = (bid - R_FILL) * 256 + tid;
        if (idx < 399360) {
            int x = idx & 127;
            int rr = idx >> 7;
            int yy = (rr & 1) ? 129 : 0;
            int kxnc = rr >> 1;
            int c = kxnc % 65;
            int nn = (kxnc / 65) & 7;
            int kx = kxnc / (65 * 8);
            g_Xs[kx * KXS + nn * NS + c * CS + yy * 128 + x] = 0;
        } else if (idx < 399360 + 2 * 67600) {
            int j = idx - 399360;
            int set = j / 67600;
            int jj = j % 67600;
            int yy = jj % 130;
            int c = (jj / 130) % 65;
            int nn = jj / (130 * 65);
            int kx = set ? 2 : 0;
            int x = set ? 127 : 0;
            g_Xs[kx * KXS + nn * NS + c * CS + yy * 128 + x] = 0;
        }
    } else if (bid < R_WS) {
        int idx = (bid - R_ZERO) * 256 + tid;   // < NCH*16384
        int c = idx >> 14;
        int r = idx & 16383;
        int m = r >> 6, q = r & 63;
        int kg = c * CHUNK + q;
        float v = (kg < KREAL) ? w1[m * KREAL + kg] : 0.f;
        int off = m * 128 + q * 2;
        int sw = off ^ ((off >> 3) & 0x70);
        ((uint16_t*)g_wBh4)[c * 16384 + (sw >> 1)] =
            __half_as_ushort(__float2half_rn(v));
    } else {
        int idx = (bid - R_WS) * 256 + tid;
        int o = (idx >> 14) & 1;
        outp[idx] = b2[o];
    }
}

// ---------------- scattered = segment_sum (smem-tiled Fx) ----------------
__global__ void k_scatter(float* __restrict__ out_scat) {
    int n = blockIdx.y, y0 = blockIdx.x * 8, x = threadIdx.x;
    __shared__ float s_fy[NV][8];
    __shared__ float s_fx[32][128];
    float acc[8];
    #pragma unroll
    for (int r = 0; r < 8; r++) acc[r] = 0.f;
    for (int c = 0; c < NC; c++) {
        if (g_batch[c] != n) continue;
        __syncthreads();
        for (int idx = x; idx < NV * 8; idx += 128) {
            int v = idx >> 3, r = idx & 7;
            s_fy[v][r] = g_Fy[(c * NV + v) * HH + (y0 + r)];
        }
        for (int vb = 0; vb < 4; vb++) {
            __syncthreads();
            for (int i = 0; i < 32; i++)
                s_fx[i][x] = g_Fx[(c * NV + vb * 32 + i) * WW + x];
            __syncthreads();
            #pragma unroll 4
            for (int vv = 0; vv < 32; vv++) {
                float fx = s_fx[vv][x];
                int v = vb * 32 + vv;
                #pragma unroll
                for (int r = 0; r < 8; r++) acc[r] += fx * s_fy[v][r];
            }
        }
    }
    #pragma unroll
    for (int r = 0; r < 8; r++) {
        out_scat[(n * HH + y0 + r) * WW + x] = acc[r];
        uint16_t v = __half_as_ushort(__float2half_rn(acc[r]));
        int base = n * NS + 0 * CS + (y0 + r + 1) * 128;
        #pragma unroll
        for (int kx = 0; kx < 3; kx++) {
            int xq = x + 1 - kx;
            if (xq >= 0 && xq < 128) g_Xs[kx * KXS + base + xq] = v;
        }
    }
}

// ---------------- HMMA conv kernel: CTA = (row, px-half, ch-half) ----------
// D[64 px, 128 ch] per CTA; 4 CTAs/SM. A 8KB x2, B 16KB x2 = 48KB dyn smem.
#define DSMEM_BYTES (49152 + 1024)

__global__ void __launch_bounds__(256, 4)
k_conv_mma(const float* __restrict__ b1, const float* __restrict__ w2,
           float* __restrict__ outp) {
    extern __shared__ char dsm[];
    __shared__ int   s_off[KPAD];
    __shared__ float s_b1[128];
    __shared__ float s_w2[256];
    __shared__ float s_part[64 * 2];

    const int tid  = threadIdx.x;
    const int wid  = tid >> 5;
    const int lane = tid & 31;
    const int gid  = lane >> 2;       // 0..7
    const int tq   = lane & 3;        // 0..3
    const int wm   = wid >> 2;        // 0..1 (px 32-block)
    const int wn   = wid & 3;         // 0..3 (32 ch each)
    const int bid  = blockIdx.x;
    const int row  = bid >> 2;
    const int ph   = (bid >> 1) & 1;  // px half (64 px)
    const int chh  = bid & 1;         // ch half (128 ch)
    const int n = row >> 7;
    const int y = row & 127;
    const int chbase = chh * 128;

    const uint32_t sbu = smem_u32(dsm);
    const uint32_t pad = (1024u - (sbu & 1023u)) & 1023u;
    const uint32_t base = sbu + pad;
    // A buffers: +buf*8192 ; B buffers: +16384 + buf*16384

    for (int i = tid; i < 128; i += 256) {
        s_b1[i] = b1[chbase + i];
        s_w2[i] = w2[chbase + i];
        s_w2[128 + i] = w2[CMID + chbase + i];
    }
    if (tid < 128) s_part[tid] = 0.f;
    for (int k = tid; k < KPAD; k += 256) {
        int off = -1;
        if (k < KREAL) {
            int ci = k / 9, pos = k - ci * 9;
            int ky = pos / 3, kx = pos - ky * 3;
            off = kx * KXS + ci * CS + ky * 128;
        }
        s_off[k] = off;
    }

    float acc[2][4][4];
    #pragma unroll
    for (int mt = 0; mt < 2; mt++)
        #pragma unroll
        for (int nt = 0; nt < 4; nt++)
            #pragma unroll
            for (int r = 0; r < 4; r++) acc[mt][nt][r] = 0.f;

    const int xbase = n * NS + y * 128 + ph * 64;

    // ---- hoisted ldmatrix address components (all ks-affine) ----
    const int g8 = lane >> 3;
    const int j8 = lane & 7;
    const int koff8 = (g8 >> 1) * 8;
    const int clane = g8 & 1;
    const int rbase = j8 + koff8;          // k row for ks=0 (0..15)
    uint32_t adbase[2];                     // A smem offset at ks=0
    #pragma unroll
    for (int mt = 0; mt < 2; mt++) {
        int chunk = wm * 4 + mt * 2 + clane;
        adbase[mt] = (uint32_t)(rbase * 128 + ((chunk ^ (rbase & 7)) << 4));
    }
    const int browx4 = (lane & 7) + ((lane >> 4) << 3);
    const int bcolsel = ((lane >> 3) & 1) * 16;
    const int bsw = (lane & 7) * 16;
    uint32_t bdrow[2];
    #pragma unroll
    for (int p = 0; p < 2; p++)
        bdrow[p] = (uint32_t)((wn * 32 + p * 16 + browx4) * 128);
    uint32_t col4[4];
    #pragma unroll
    for (int ks = 0; ks < 4; ks++)
        col4[ks] = (uint32_t)((ks * 32 + bcolsel) ^ bsw);

#define STAGE_A(k0, aA)                                                        \
    do {                                                                       \
        _Pragma("unroll")                                                      \
        for (int t = 0; t < 2; t++) {                                          \
            int idx = tid + t * 256;                                           \
            int rowi = idx >> 3;               /* 0..63 = k */                 \
            int c8 = idx & 7;                                                  \
            int off = s_off[(k0) + rowi];                                      \
            uint32_t sz = (off >= 0) ? 16u : 0u;                               \
            const uint16_t* src = g_Xs + (xbase + (off >= 0 ? off : 0)         \
                                          + c8 * 8);                           \
            uint32_t dst = (aA) + rowi * 128 + ((c8 ^ (rowi & 7)) << 4);       \
            CP_ASYNC16Z(dst, src, sz);                                         \
        }                                                                      \
    } while (0)

#define STAGE_B(c, aB)                                                         \
    do {                                                                       \
        const char* src = (const char*)(g_wBh4 + (c) * 2048 + chh * 1024);     \
        _Pragma("unroll")                                                      \
        for (int i = 0; i < 4; i++) {                                          \
            int gi = tid + i * 256;                                            \
            CP_ASYNC16((aB) + gi * 16, src + gi * 16);                         \
        }                                                                      \
    } while (0)

    __syncthreads();
    STAGE_A(0, base);
    STAGE_B(0, base + 16384u);
    CP_COMMIT();
    CP_WAIT0();
    __syncthreads();

    for (int c = 0; c < NCH; c++) {
        const int cur = c & 1;
        const uint32_t aA = base + (uint32_t)cur * 8192u;
        const uint32_t aB = base + 16384u + (uint32_t)cur * 16384u;

        if (c < NCH - 1) {
            const int nxt = cur ^ 1;
            STAGE_A((c + 1) * CHUNK, base + (uint32_t)nxt * 8192u);
            STAGE_B(c + 1, base + 16384u + (uint32_t)nxt * 16384u);
            CP_COMMIT();
        }

        const int nks = (c == NCH - 1) ? 1 : 4;
        #pragma unroll
        for (int ks = 0; ks < 4; ks++) {
            if (ks >= nks) break;
            uint32_t Af[2][4];
            #pragma unroll
            for (int mt = 0; mt < 2; mt++)
                ldm_x4_trans(Af[mt], aA + adbase[mt] + (uint32_t)(ks * 2048));
            uint32_t Bf[2][4];
            #pragma unroll
            for (int p = 0; p < 2; p++)
                ldm_x4(Bf[p], aB + bdrow[p] + col4[ks]);
            #pragma unroll
            for (int p = 0; p < 2; p++)
                #pragma unroll
                for (int q = 0; q < 2; q++)
                    #pragma unroll
                    for (int mt = 0; mt < 2; mt++)
                        mma_fp16(acc[mt][p * 2 + q], Af[mt], &Bf[p][q * 2]);
        }
        CP_WAIT0();
        __syncthreads();
    }

    // epilogue: relu(D + b1) -> partial 1x1 conv, reduce in smem, atomicAdd gmem
    #pragma unroll
    for (int mt = 0; mt < 2; mt++) {
        #pragma unroll
        for (int half = 0; half < 2; half++) {
            float s0 = 0.f, s1 = 0.f;
            #pragma unroll
            for (int nt = 0; nt < 4; nt++) {
                int cl = wn * 32 + nt * 8 + tq * 2;
                float h0 = fmaxf(acc[mt][nt][half * 2 + 0] + s_b1[cl], 0.f);
                float h1 = fmaxf(acc[mt][nt][half * 2 + 1] + s_b1[cl + 1], 0.f);
                s0 += h0 * s_w2[cl] + h1 * s_w2[cl + 1];
                s1 += h0 * s_w2[128 + cl] + h1 * s_w2[128 + cl + 1];
            }
            s0 += __shfl_xor_sync(0xffffffffu, s0, 1);
            s0 += __shfl_xor_sync(0xffffffffu, s0, 2);
            s1 += __shfl_xor_sync(0xffffffffu, s1, 1);
            s1 += __shfl_xor_sync(0xffffffffu, s1, 2);
            if (tq == 0) {
                int px = wm * 32 + mt * 16 + half * 8 + gid;   // 0..63
                atomicAdd(&s_part[px * 2 + 0], s0);
                atomicAdd(&s_part[px * 2 + 1], s1);
            }
        }
    }
    __syncthreads();
    if (tid < 128) {
        int px = tid >> 1, o = tid & 1;
        atomicAdd(&outp[((n * 2 + o) * HH + y) * WW + ph * 64 + px],
                  s_part[px * 2 + o]);
    }
}

// ---------------- launch ----------------
extern "C" void kernel_launch(void* const* d_in, const int* in_sizes, int n_in,
                              void* d_out, int out_size) {
    const float* contour = (const float*)d_in[0];
    const float* feature = (const float*)d_in[1];
    const int*   batchi  = (const int*)d_in[2];
    const float* w1      = (const float*)d_in[3];
    const float* b1      = (const float*)d_in[4];
    const float* w2      = (const float*)d_in[5];
    const float* b2      = (const float*)d_in[6];
    float* out = (float*)d_out;
    float* out_scat = out + NIMG * 2 * HH * WW;

    static int attr_set = 0;
    if (!attr_set) {
        cudaFuncSetAttribute(k_conv_mma,
                             cudaFuncAttributeMaxDynamicSharedMemorySize,
                             DSMEM_BYTES);
        attr_set = 1;
    }

    k_prep<<<R_OINIT, 256>>>(contour, batchi, feature, w1, b2, out);
    k_scatter<<<dim3(HH / 8, NIMG), 128>>>(out_scat);
    k_conv_mma<<<4096, 256, DSMEM_BYTES>>>(b1, w2, out);
}